// round 13
// baseline (speedup 1.0000x reference)
#include <cuda_runtime.h>
#include <cuda_bf16.h>
#include <math.h>

#define V_  32000
#define D_  512
#define H_  8
#define DFF_ 2048
#define L_  2
#define B_  16
#define LIN_ 400
#define T_  100
#define DEPTH_ 64
#define VEXT_ 32100
#define SQRT_D 22.627416997969522f
#define QKV_SZ (B_*LIN_*D_)

// ---------------------------------------------------------------------------
// Scratch
// ---------------------------------------------------------------------------
__device__ __align__(16) float g_pe   [LIN_ * D_];
__device__ __align__(16) float g_encx [B_*LIN_ * D_];
__device__ __align__(16) float g_qkv  [3 * QKV_SZ];
__device__ __align__(16) float g_attno[B_*LIN_ * D_];
__device__ __align__(16) float g_tmp  [B_*LIN_ * D_];
__device__ __align__(16) float g_ffn  [B_*LIN_ * DFF_];
__device__ __align__(16) float g_decx [B_*T_ * D_];
__device__ __align__(16) float g_o1   [B_*T_ * D_];
__device__ __align__(16) float g_embed[B_*T_ * D_];
__device__ __align__(16) float g_block2[B_*H_*T_*LIN_];
__device__ __align__(16) float g_ctx  [B_*T_ * D_];
__device__ float g_pg   [B_*T_];

// ---------------------------------------------------------------------------
__global__ void pe_kernel(float* pe) {
    int idx = blockIdx.x * blockDim.x + threadIdx.x;
    if (idx >= LIN_ * D_) return;
    int pos = idx >> 9;
    int d   = idx & (D_ - 1);
    // rate = 10000^(-2*(d/2)/512) ; fp32 is plenty (abs err ~1e-5 on O(1) vals)
    float k2 = (float)(2 * (d >> 1)) * (1.0f / 512.0f);
    float rate = exp2f(-k2 * 13.287712379549449f);   // log2(10000)
    float ang = (float)pos * rate;
    pe[idx] = (d & 1) ? cosf(ang) : sinf(ang);
}

__global__ void embed_kernel(const int* __restrict__ tok,
                             const float* __restrict__ emb,
                             const float* __restrict__ pe,
                             float* __restrict__ x,
                             float* __restrict__ raw,
                             int S, int count) {
    int idx = blockIdx.x * blockDim.x + threadIdx.x;
    if (idx >= count) return;
    int d  = idx & (D_ - 1);
    int bs = idx >> 9;
    int s  = bs % S;
    float e = emb[(size_t)tok[bs] * D_ + d];
    if (raw) raw[idx] = e;
    x[idx] = e * SQRT_D + pe[s * D_ + d];
}

// ---------------------------------------------------------------------------
// TF32 tensor-core GEMM with cp.async 2-stage pipeline.
// C[M,*](ldc) = rowscale * (A[M,K] @ W + bias), opt ReLU.
// Grouped-N: column block n0 belongs to group n0/Ninner; W/bias/C advance by
// wgs/bgs/cgs per group (fused QKV projections). Normal GEMM: Ninner=N, 0,0,0.
// ---------------------------------------------------------------------------
#define SA_STRIDE 20    // 80B rows (16B-aligned, conflict-free frags)
#define SB_STRIDE 136   // 544B rows (16B-aligned, conflict-free frags)

__device__ __forceinline__ float to_tf32(float x) {
    float r;
    asm("cvt.rna.tf32.f32 %0, %1;" : "=f"(r) : "f"(x));
    return r;
}

#define CPA(dst, src, sz) \
    asm volatile("cp.async.ca.shared.global [%0], [%1], 16, %2;\n" \
                 :: "r"(dst), "l"(src), "r"(sz))

template<int WMW>
__global__ __launch_bounds__(256) void gemm_tf32(
    const float* __restrict__ A, const float* __restrict__ Wp,
    const float* __restrict__ biasp, const float* __restrict__ rowscale,
    float* __restrict__ Cp,
    int M, int K, int ldc, int relu,
    int Ninner, long wgs, long bgs, long cgs)
{
    constexpr int WNW = 8 / WMW;          // warps along N
    constexpr int BMt = WMW * 32;         // 128 or 64
    constexpr int NI  = 128 / (WNW * 8);  // n-frags per warp
    constexpr int AV  = BMt / 64;         // A cp.async per thread

    __shared__ __align__(16) float sA[2][BMt * SA_STRIDE];
    __shared__ __align__(16) float sB[2][16 * SB_STRIDE];

    int tid  = threadIdx.x;
    int wid  = tid >> 5;
    int lane = tid & 31;
    int wm = wid / WNW;
    int wn = wid % WNW;
    int g  = lane >> 2;
    int tg = lane & 3;

    int m0 = blockIdx.y * BMt;
    int n0 = blockIdx.x * 128;
    int grp = n0 / Ninner;
    int nl  = n0 - grp * Ninner;
    const float* W    = Wp    + (size_t)grp * wgs;
    const float* bias = biasp + (size_t)grp * bgs;
    float*       C    = Cp    + (size_t)grp * cgs;

    float acc[2][NI][4];
    #pragma unroll
    for (int mi = 0; mi < 2; mi++)
        #pragma unroll
        for (int ni = 0; ni < NI; ni++)
            #pragma unroll
            for (int r = 0; r < 4; r++) acc[mi][ni][r] = 0.f;

    int ntiles = K >> 4;

    // -------- issue stage 0 --------
    {
        #pragma unroll
        for (int r = 0; r < AV; r++) {
            int i = tid + r * 256;
            int row = i >> 2, c4 = (i & 3) * 4;
            unsigned dst = (unsigned)__cvta_generic_to_shared(&sA[0][row * SA_STRIDE + c4]);
            const float* src = A + (size_t)(m0 + row) * K + c4;
            CPA(dst, src, (m0 + row < M) ? 16 : 0);
        }
        #pragma unroll
        for (int r = 0; r < 2; r++) {
            int i = tid + r * 256;
            int row = i >> 5, c4 = (i & 31) * 4;
            unsigned dst = (unsigned)__cvta_generic_to_shared(&sB[0][row * SB_STRIDE + c4]);
            const float* src = W + (size_t)row * Ninner + nl + c4;
            CPA(dst, src, 16);
        }
        asm volatile("cp.async.commit_group;\n");
    }

    for (int kt = 0; kt < ntiles; kt++) {
        int cur = kt & 1;
        if (kt + 1 < ntiles) {
            int nxt = cur ^ 1;
            int kof = (kt + 1) * 16;
            #pragma unroll
            for (int r = 0; r < AV; r++) {
                int i = tid + r * 256;
                int row = i >> 2, c4 = (i & 3) * 4;
                unsigned dst = (unsigned)__cvta_generic_to_shared(&sA[nxt][row * SA_STRIDE + c4]);
                const float* src = A + (size_t)(m0 + row) * K + kof + c4;
                CPA(dst, src, (m0 + row < M) ? 16 : 0);
            }
            #pragma unroll
            for (int r = 0; r < 2; r++) {
                int i = tid + r * 256;
                int row = i >> 5, c4 = (i & 31) * 4;
                unsigned dst = (unsigned)__cvta_generic_to_shared(&sB[nxt][row * SB_STRIDE + c4]);
                const float* src = W + (size_t)(kof + row) * Ninner + nl + c4;
                CPA(dst, src, 16);
            }
            asm volatile("cp.async.commit_group;\n");
            asm volatile("cp.async.wait_group 1;\n");
        } else {
            asm volatile("cp.async.wait_group 0;\n");
        }
        __syncthreads();

        const float* cA = sA[cur];
        const float* cB = sB[cur];
        #pragma unroll
        for (int ks = 0; ks < 16; ks += 8) {
            unsigned af[2][4];
            #pragma unroll
            for (int mi = 0; mi < 2; mi++) {
                int bm = wm * 32 + mi * 16;
                af[mi][0] = __float_as_uint(to_tf32(cA[(bm + g    ) * SA_STRIDE + ks + tg    ]));
                af[mi][1] = __float_as_uint(to_tf32(cA[(bm + g + 8) * SA_STRIDE + ks + tg    ]));
                af[mi][2] = __float_as_uint(to_tf32(cA[(bm + g    ) * SA_STRIDE + ks + tg + 4]));
                af[mi][3] = __float_as_uint(to_tf32(cA[(bm + g + 8) * SA_STRIDE + ks + tg + 4]));
            }
            unsigned bf[NI][2];
            #pragma unroll
            for (int ni = 0; ni < NI; ni++) {
                int bn = wn * (NI * 8) + ni * 8 + g;
                bf[ni][0] = __float_as_uint(to_tf32(cB[(ks + tg    ) * SB_STRIDE + bn]));
                bf[ni][1] = __float_as_uint(to_tf32(cB[(ks + tg + 4) * SB_STRIDE + bn]));
            }
            #pragma unroll
            for (int mi = 0; mi < 2; mi++)
                #pragma unroll
                for (int ni = 0; ni < NI; ni++) {
                    float* c = acc[mi][ni];
                    asm volatile(
                        "mma.sync.aligned.m16n8k8.row.col.f32.tf32.tf32.f32 "
                        "{%0,%1,%2,%3}, {%4,%5,%6,%7}, {%8,%9}, {%0,%1,%2,%3};\n"
                        : "+f"(c[0]), "+f"(c[1]), "+f"(c[2]), "+f"(c[3])
                        : "r"(af[mi][0]), "r"(af[mi][1]), "r"(af[mi][2]), "r"(af[mi][3]),
                          "r"(bf[ni][0]), "r"(bf[ni][1]));
                }
        }
        __syncthreads();
    }

    // epilogue
    #pragma unroll
    for (int mi = 0; mi < 2; mi++) {
        int r0 = m0 + wm * 32 + mi * 16 + g;
        int r1 = r0 + 8;
        float rs0 = 1.f, rs1 = 1.f;
        if (rowscale) {
            if (r0 < M) rs0 = rowscale[r0];
            if (r1 < M) rs1 = rowscale[r1];
        }
        #pragma unroll
        for (int ni = 0; ni < NI; ni++) {
            int cc = wn * (NI * 8) + ni * 8 + 2 * tg;
            float b0 = bias[nl + cc], b1 = bias[nl + cc + 1];
            float v0 = (acc[mi][ni][0] + b0) * rs0;
            float v1 = (acc[mi][ni][1] + b1) * rs0;
            float v2 = (acc[mi][ni][2] + b0) * rs1;
            float v3 = (acc[mi][ni][3] + b1) * rs1;
            if (relu) {
                v0 = fmaxf(v0, 0.f); v1 = fmaxf(v1, 0.f);
                v2 = fmaxf(v2, 0.f); v3 = fmaxf(v3, 0.f);
            }
            if (r0 < M) { C[(size_t)r0 * ldc + nl + cc] = v0; C[(size_t)r0 * ldc + nl + cc + 1] = v1; }
            if (r1 < M) { C[(size_t)r1 * ldc + nl + cc] = v2; C[(size_t)r1 * ldc + nl + cc + 1] = v3; }
        }
    }
}

// ---------------------------------------------------------------------------
// Tiled attention (conflict-free scores), unchanged from R10.
// ---------------------------------------------------------------------------
#define KV_STRIDE 68
#define Q_STRIDE  68
__global__ __launch_bounds__(128) void attn_tiled(
    const float* __restrict__ Q, const float* __restrict__ Kt,
    const float* __restrict__ Vt, const float* __restrict__ mask,
    int mask_mode, float* __restrict__ Out, float* __restrict__ attn_save,
    const float* __restrict__ V2, float* __restrict__ Out2,
    int Sq, int Skv)
{
    int nqt = (Sq + 15) >> 4;
    int qt = blockIdx.x % nqt;
    int h  = (blockIdx.x / nqt) % H_;
    int b  = blockIdx.x / (nqt * H_);
    int i0 = qt * 16;
    int tid = threadIdx.x;
    int wid = tid >> 5;
    int lane = tid & 31;

    __shared__ __align__(16) float sQ[16][Q_STRIDE];
    __shared__ __align__(16) float sS[16][LIN_ + 8];
    __shared__ __align__(16) float sKV[64][KV_STRIDE];

    #pragma unroll
    for (int r = 0; r < 2; r++) {
        int i = tid + r * 128;
        int row = i >> 4, c4 = (i & 15) * 4;
        float4 v = make_float4(0.f, 0.f, 0.f, 0.f);
        if (i0 + row < Sq)
            v = *(const float4*)(Q + (size_t)(b * Sq + i0 + row) * D_ + h * DEPTH_ + c4);
        *(float4*)(&sQ[row][c4]) = v;
    }
    __syncthreads();

    int nchunks = (Skv + 63) >> 6;
    int myq = tid >> 3;
    int jt  = tid & 7;

    for (int jc = 0; jc < nchunks; jc++) {
        int jbase = jc * 64;
        #pragma unroll
        for (int r = 0; r < 8; r++) {
            int i = tid + r * 128;
            int row = i >> 4, c4 = (i & 15) * 4;
            float4 v = make_float4(0.f, 0.f, 0.f, 0.f);
            if (jbase + row < Skv)
                v = *(const float4*)(Kt + (size_t)(b * Skv + jbase + row) * D_ + h * DEPTH_ + c4);
            *(float4*)(&sKV[row][c4]) = v;
        }
        __syncthreads();
        float qacc[8];
        #pragma unroll
        for (int jj = 0; jj < 8; jj++) qacc[jj] = 0.f;
        #pragma unroll 4
        for (int d = 0; d < 64; d++) {
            float qd = sQ[myq][d];
            #pragma unroll
            for (int jj = 0; jj < 8; jj++)
                qacc[jj] += qd * sKV[jt + 8 * jj][d];
        }
        int iq = i0 + myq; if (iq >= Sq) iq = Sq - 1;
        #pragma unroll
        for (int jj = 0; jj < 8; jj++) {
            int j = jbase + jt + 8 * jj;
            if (j < Skv) {
                float mv = (mask_mode == 1)
                    ? mask[((size_t)b * Sq + iq) * Skv + j]
                    : mask[(size_t)b * Skv + j];
                sS[myq][j] = qacc[jj] * 0.125f + mv * -1e9f;
            }
        }
        __syncthreads();
    }

    for (int q = wid; q < 16; q += 4) {
        float mx = -INFINITY;
        for (int j = lane; j < Skv; j += 32) mx = fmaxf(mx, sS[q][j]);
        #pragma unroll
        for (int o = 16; o > 0; o >>= 1)
            mx = fmaxf(mx, __shfl_xor_sync(0xffffffff, mx, o));
        float sum = 0.f;
        for (int j = lane; j < Skv; j += 32) {
            float e = expf(sS[q][j] - mx);
            sS[q][j] = e;
            sum += e;
        }
        #pragma unroll
        for (int o = 16; o > 0; o >>= 1)
            sum += __shfl_xor_sync(0xffffffff, sum, o);
        float inv = 1.f / sum;
        for (int j = lane; j < Skv; j += 32) sS[q][j] *= inv;
    }
    __syncthreads();

    if (attn_save && i0 + myq < Sq) {
        size_t base = (((size_t)(b * H_ + h) * Sq) + i0 + myq) * Skv;
        for (int j = jt; j < Skv; j += 8)
            attn_save[base + j] = sS[myq][j];
    }

    int d8 = jt * 8;
    float acc[8], acc2[8];
    #pragma unroll
    for (int r = 0; r < 8; r++) { acc[r] = 0.f; acc2[r] = 0.f; }

    for (int jc = 0; jc < nchunks; jc++) {
        int jbase = jc * 64;
        int jn = Skv - jbase; if (jn > 64) jn = 64;
        __syncthreads();
        #pragma unroll
        for (int r = 0; r < 8; r++) {
            int i = tid + r * 128;
            int row = i >> 4, c4 = (i & 15) * 4;
            float4 v = make_float4(0.f, 0.f, 0.f, 0.f);
            if (jbase + row < Skv)
                v = *(const float4*)(Vt + (size_t)(b * Skv + jbase + row) * D_ + h * DEPTH_ + c4);
            *(float4*)(&sKV[row][c4]) = v;
        }
        __syncthreads();
        for (int jj = 0; jj < jn; jj++) {
            float p = sS[myq][jbase + jj];
            #pragma unroll
            for (int dd = 0; dd < 8; dd++)
                acc[dd] += p * sKV[jj][d8 + dd];
        }
        if (V2) {
            __syncthreads();
            #pragma unroll
            for (int r = 0; r < 8; r++) {
                int i = tid + r * 128;
                int row = i >> 4, c4 = (i & 15) * 4;
                float4 v = make_float4(0.f, 0.f, 0.f, 0.f);
                if (jbase + row < Skv)
                    v = *(const float4*)(V2 + (size_t)(b * Skv + jbase + row) * D_ + h * DEPTH_ + c4);
                *(float4*)(&sKV[row][c4]) = v;
            }
            __syncthreads();
            for (int jj = 0; jj < jn; jj++) {
                float p = sS[myq][jbase + jj];
                #pragma unroll
                for (int dd = 0; dd < 8; dd++)
                    acc2[dd] += p * sKV[jj][d8 + dd];
            }
        }
    }
    if (i0 + myq < Sq) {
        size_t base = (size_t)(b * Sq + i0 + myq) * D_ + h * DEPTH_ + d8;
        #pragma unroll
        for (int dd = 0; dd < 8; dd++) Out[base + dd] = acc[dd];
        if (Out2)
            #pragma unroll
            for (int dd = 0; dd < 8; dd++) Out2[base + dd] = acc2[dd];
    }
}

// ---------------------------------------------------------------------------
__global__ __launch_bounds__(128) void add_ln(
    const float* __restrict__ X, const float* __restrict__ A,
    const float* __restrict__ g, const float* __restrict__ beta,
    float* __restrict__ Y)
{
    int row = blockIdx.x;
    int tid = threadIdx.x;
    __shared__ float red[128];
    size_t base = (size_t)row * D_;
    float v[4];
    float s = 0.f;
    #pragma unroll
    for (int k = 0; k < 4; k++) {
        v[k] = X[base + tid + k * 128] + A[base + tid + k * 128];
        s += v[k];
    }
    red[tid] = s; __syncthreads();
    for (int st = 64; st > 0; st >>= 1) {
        if (tid < st) red[tid] += red[tid + st];
        __syncthreads();
    }
    float mu = red[0] * (1.f / D_);
    __syncthreads();
    float vs = 0.f;
    #pragma unroll
    for (int k = 0; k < 4; k++) { float d = v[k] - mu; vs += d * d; }
    red[tid] = vs; __syncthreads();
    for (int st = 64; st > 0; st >>= 1) {
        if (tid < st) red[tid] += red[tid + st];
        __syncthreads();
    }
    float inv = rsqrtf(red[0] * (1.f / D_) + 1e-6f);
    #pragma unroll
    for (int k = 0; k < 4; k++) {
        int c = tid + k * 128;
        Y[base + c] = (v[k] - mu) * inv * g[c] + beta[c];
    }
}

__global__ __launch_bounds__(128) void pgen_kernel(
    const float* __restrict__ ctx, const float* __restrict__ dec,
    const float* __restrict__ emb, const float* __restrict__ ptrw,
    const float* __restrict__ ptrb, float* __restrict__ pg)
{
    int row = blockIdx.x;
    int tid = threadIdx.x;
    __shared__ float red[128];
    size_t base = (size_t)row * D_;
    float s = 0.f;
    for (int c = tid; c < D_; c += 128)
        s += ctx[base + c] * ptrw[c] + dec[base + c] * ptrw[D_ + c]
           + emb[base + c] * ptrw[2 * D_ + c];
    red[tid] = s; __syncthreads();
    for (int st = 64; st > 0; st >>= 1) {
        if (tid < st) red[tid] += red[tid + st];
        __syncthreads();
    }
    if (tid == 0) {
        float z = red[0] + ptrb[0] + ptrb[1] + ptrb[2];
        pg[row] = 1.f / (1.f + expf(-z));
    }
}

__global__ __launch_bounds__(128) void attn_mean_kernel(
    const float* __restrict__ block2, float* __restrict__ out2)
{
    int row = blockIdx.x;
    int b = row / T_, t = row % T_;
    for (int l = threadIdx.x; l < LIN_; l += 128) {
        float s = 0.f;
        #pragma unroll
        for (int h = 0; h < H_; h++)
            s += block2[((size_t)(b * H_ + h) * T_ + t) * LIN_ + l];
        out2[(size_t)row * LIN_ + l] = s * 0.125f;
    }
}

__global__ void zero_tail_kernel(float* __restrict__ out) {
    int idx = blockIdx.x * blockDim.x + threadIdx.x;
    if (idx >= B_ * T_ * 100) return;
    int row = idx / 100;
    int t   = idx % 100;
    out[(size_t)row * VEXT_ + V_ + t] = 0.f;
}

__global__ void scatter_kernel(float* __restrict__ out,
                               const float* __restrict__ am,
                               const float* __restrict__ pg,
                               const int* __restrict__ ext)
{
    int idx = blockIdx.x * blockDim.x + threadIdx.x;
    if (idx >= B_ * T_ * LIN_) return;
    int l = idx % LIN_;
    int row = idx / LIN_;
    int b = row / T_;
    float q = 1.f - pg[row];
    atomicAdd(&out[(size_t)row * VEXT_ + ext[(size_t)b * LIN_ + l]],
              q * am[(size_t)row * LIN_ + l]);
}

// ---------------------------------------------------------------------------
static inline void gemmN(const float* A, const float* W, const float* bias,
                         const float* rs, float* C, int M, int Ntot, int K,
                         int ldc, int relu,
                         int Ninner, long wgs, long bgs, long cgs) {
    if (M >= 3200 || Ntot >= 4096) {
        dim3 grid(Ntot / 128, (M + 127) / 128);
        gemm_tf32<4><<<grid, 256>>>(A, W, bias, rs, C, M, K, ldc, relu,
                                    Ninner, wgs, bgs, cgs);
    } else {
        dim3 grid(Ntot / 128, (M + 63) / 64);
        gemm_tf32<2><<<grid, 256>>>(A, W, bias, rs, C, M, K, ldc, relu,
                                    Ninner, wgs, bgs, cgs);
    }
}
static inline void gemm(const float* A, const float* W, const float* bias,
                        const float* rs, float* C, int M, int N, int K,
                        int ldc, int relu) {
    gemmN(A, W, bias, rs, C, M, N, K, ldc, relu, N, 0, 0, 0);
}

extern "C" void kernel_launch(void* const* d_in, const int* in_sizes, int n_in,
                              void* d_out, int out_size) {
    const int*   inp     = (const int*)d_in[0];
    const int*   tar     = (const int*)d_in[1];
    const int*   ext     = (const int*)d_in[2];
    const float* enc_pad = (const float*)d_in[3];
    const float* look    = (const float*)d_in[4];
    const float* dec_pad = (const float*)d_in[5];
    int o = (in_sizes[6] <= 4) ? 7 : 6;
    const float* emb_enc = (const float*)d_in[o + 0];
    const float* emb_dec = (const float*)d_in[o + 1];
    const float* eaw  = (const float*)d_in[o + 2];
    const float* eab  = (const float*)d_in[o + 3];
    const float* ew1  = (const float*)d_in[o + 4];
    const float* eb1  = (const float*)d_in[o + 5];
    const float* ew2  = (const float*)d_in[o + 6];
    const float* eb2  = (const float*)d_in[o + 7];
    const float* elng = (const float*)d_in[o + 8];
    const float* elnb = (const float*)d_in[o + 9];
    const float* daw  = (const float*)d_in[o + 10];
    const float* dab  = (const float*)d_in[o + 11];
    const float* dw1  = (const float*)d_in[o + 12];
    const float* db1  = (const float*)d_in[o + 13];
    const float* dw2  = (const float*)d_in[o + 14];
    const float* db2  = (const float*)d_in[o + 15];
    const float* dlng = (const float*)d_in[o + 16];
    const float* dlnb = (const float*)d_in[o + 17];
    const float* ptrw = (const float*)d_in[o + 18];
    const float* ptrb = (const float*)d_in[o + 19];
    const float* finw = (const float*)d_in[o + 20];
    const float* finb = (const float*)d_in[o + 21];
    float* out = (float*)d_out;

    float *pe, *encx, *qkv, *attno, *tmp, *ffn, *decx, *o1buf,
          *embedr, *block2, *ctx, *pg;
    cudaGetSymbolAddress((void**)&pe,     g_pe);
    cudaGetSymbolAddress((void**)&encx,   g_encx);
    cudaGetSymbolAddress((void**)&qkv,    g_qkv);
    cudaGetSymbolAddress((void**)&attno,  g_attno);
    cudaGetSymbolAddress((void**)&tmp,    g_tmp);
    cudaGetSymbolAddress((void**)&ffn,    g_ffn);
    cudaGetSymbolAddress((void**)&decx,   g_decx);
    cudaGetSymbolAddress((void**)&o1buf,  g_o1);
    cudaGetSymbolAddress((void**)&embedr, g_embed);
    cudaGetSymbolAddress((void**)&block2, g_block2);
    cudaGetSymbolAddress((void**)&ctx,    g_ctx);
    cudaGetSymbolAddress((void**)&pg,     g_pg);

    float* q = qkv;
    float* k = qkv + QKV_SZ;
    float* v = qkv + 2 * QKV_SZ;

    const int ME = B_ * LIN_;  // 6400
    const int MD = B_ * T_;    // 1600
    const long DD = (long)D_ * D_;

    pe_kernel<<<(LIN_ * D_ + 255) / 256, 256>>>(pe);
    embed_kernel<<<(ME * D_ + 255) / 256, 256>>>(inp, emb_enc, pe, encx,
                                                 nullptr, LIN_, ME * D_);
    embed_kernel<<<(MD * D_ + 255) / 256, 256>>>(tar, emb_dec, pe, decx,
                                                 embedr, T_, MD * D_);

    // ----- encoder -----
    for (int i = 0; i < L_; i++) {
        const float* w  = eaw + (size_t)i * 4 * DD;
        const float* bb = eab + (size_t)i * 4 * D_;
        // fused QKV: one launch, 3 column groups
        gemmN(encx, w, bb, nullptr, q, ME, 3 * D_, D_, D_, 0,
              D_, DD, D_, QKV_SZ);
        attn_tiled<<<B_ * H_ * ((LIN_ + 15) / 16), 128>>>(
            q, k, v, enc_pad, 0, attno, nullptr, nullptr, nullptr, LIN_, LIN_);
        gemm(attno, w + 3 * DD, bb + 3 * D_, nullptr, tmp, ME, D_, D_, D_, 0);
        add_ln<<<ME, 128>>>(encx, tmp, elng + (size_t)(i * 2 + 0) * D_,
                            elnb + (size_t)(i * 2 + 0) * D_, encx);
        gemm(encx, ew1 + (size_t)i * D_ * DFF_, eb1 + (size_t)i * DFF_,
             nullptr, ffn, ME, DFF_, D_, DFF_, 1);
        gemm(ffn, ew2 + (size_t)i * DFF_ * D_, eb2 + (size_t)i * D_,
             nullptr, tmp, ME, D_, DFF_, D_, 0);
        add_ln<<<ME, 128>>>(encx, tmp, elng + (size_t)(i * 2 + 1) * D_,
                            elnb + (size_t)(i * 2 + 1) * D_, encx);
    }

    // ----- decoder: only layer L-1 affects outputs -----
    {
        const int i = L_ - 1;
        const float* w0 = daw + (size_t)(i * 2 + 0) * 4 * DD;
        const float* b0 = dab + (size_t)(i * 2 + 0) * 4 * D_;
        gemmN(decx, w0, b0, nullptr, q, MD, 3 * D_, D_, D_, 0,
              D_, DD, D_, QKV_SZ);
        attn_tiled<<<B_ * H_ * ((T_ + 15) / 16), 128>>>(
            q, k, v, look, 1, attno, nullptr, nullptr, nullptr, T_, T_);
        gemm(attno, w0 + 3 * DD, b0 + 3 * D_, nullptr, tmp, MD, D_, D_, D_, 0);
        add_ln<<<MD, 128>>>(decx, tmp, dlng + (size_t)(i * 3 + 0) * D_,
                            dlnb + (size_t)(i * 3 + 0) * D_, o1buf);
        // cross-attention; fuses context = P @ enc_heads
        const float* w1 = daw + (size_t)(i * 2 + 1) * 4 * DD;
        const float* b1 = dab + (size_t)(i * 2 + 1) * 4 * D_;
        gemm(o1buf, w1, b1, nullptr, q, MD, D_, D_, D_, 0);
        gemmN(encx, w1 + DD, b1 + D_, nullptr, k, ME, 2 * D_, D_, D_, 0,
              D_, DD, D_, QKV_SZ);
        attn_tiled<<<B_ * H_ * ((T_ + 15) / 16), 128>>>(
            q, k, v, dec_pad, 0, attno, block2, encx, ctx, T_, LIN_);
        gemm(attno, w1 + 3 * DD, b1 + 3 * D_, nullptr, tmp, MD, D_, D_, D_, 0);
        add_ln<<<MD, 128>>>(o1buf, tmp, dlng + (size_t)(i * 3 + 1) * D_,
                            dlnb + (size_t)(i * 3 + 1) * D_, o1buf);
        gemm(o1buf, dw1 + (size_t)i * D_ * DFF_, db1 + (size_t)i * DFF_,
             nullptr, ffn, MD, DFF_, D_, DFF_, 1);
        gemm(ffn, dw2 + (size_t)i * DFF_ * D_, db2 + (size_t)i * D_,
             nullptr, tmp, MD, D_, DFF_, D_, 0);
        add_ln<<<MD, 128>>>(o1buf, tmp, dlng + (size_t)(i * 3 + 2) * D_,
                            dlnb + (size_t)(i * 3 + 2) * D_, decx);
    }

    // ----- pointer-generator prob, head with fused p*logits -----
    pgen_kernel<<<MD, 128>>>(ctx, decx, embedr, ptrw, ptrb, pg);
    gemm(decx, finw, finb, pg, out, MD, V_, D_, VEXT_, 0);
    zero_tail_kernel<<<(MD * 100 + 255) / 256, 256>>>(out);

    float* out2 = out + (size_t)MD * VEXT_;
    attn_mean_kernel<<<MD, 128>>>(block2, out2);
    scatter_kernel<<<(B_ * T_ * LIN_ + 255) / 256, 256>>>(out, out2, pg, ext);
}

// round 14
// speedup vs baseline: 1.5221x; 1.5221x over previous
#include <cuda_runtime.h>
#include <cuda_bf16.h>
#include <math.h>

#define V_  32000
#define D_  512
#define H_  8
#define DFF_ 2048
#define L_  2
#define B_  16
#define LIN_ 400
#define T_  100
#define DEPTH_ 64
#define VEXT_ 32100
#define SQRT_D 22.627416997969522f
#define QKV_SZ (B_*LIN_*D_)

// ---------------------------------------------------------------------------
// Scratch
// ---------------------------------------------------------------------------
__device__ __align__(16) float g_pe   [LIN_ * D_];
__device__ __align__(16) float g_encx [B_*LIN_ * D_];
__device__ __align__(16) float g_qkv  [3 * QKV_SZ];
__device__ __align__(16) float g_attno[B_*LIN_ * D_];
__device__ __align__(16) float g_tmp  [B_*LIN_ * D_];
__device__ __align__(16) float g_ffn  [B_*LIN_ * DFF_];
__device__ __align__(16) float g_decx [B_*T_ * D_];
__device__ __align__(16) float g_o1   [B_*T_ * D_];
__device__ __align__(16) float g_embed[B_*T_ * D_];
__device__ __align__(16) float g_block2[B_*H_*T_*LIN_];
__device__ __align__(16) float g_ctx  [B_*T_ * D_];
__device__ float g_pg   [B_*T_];

// ---------------------------------------------------------------------------
__global__ void pe_kernel(float* pe) {
    int idx = blockIdx.x * blockDim.x + threadIdx.x;
    if (idx >= LIN_ * D_) return;
    int pos = idx >> 9;
    int d   = idx & (D_ - 1);
    float k2 = (float)(2 * (d >> 1)) * (1.0f / 512.0f);
    float rate = exp2f(-k2 * 13.287712379549449f);   // log2(10000)
    float ang = (float)pos * rate;
    pe[idx] = (d & 1) ? cosf(ang) : sinf(ang);
}

__global__ void embed_kernel(const int* __restrict__ tok,
                             const float* __restrict__ emb,
                             const float* __restrict__ pe,
                             float* __restrict__ x,
                             float* __restrict__ raw,
                             int S, int count) {
    int idx = blockIdx.x * blockDim.x + threadIdx.x;
    if (idx >= count) return;
    int d  = idx & (D_ - 1);
    int bs = idx >> 9;
    int s  = bs % S;
    float e = emb[(size_t)tok[bs] * D_ + d];
    if (raw) raw[idx] = e;
    x[idx] = e * SQRT_D + pe[s * D_ + d];
}

// ---------------------------------------------------------------------------
// TF32 tensor-core GEMM, cp.async pipeline with ONE barrier per K-tile:
//   wait_group 0 -> syncthreads -> issue k+1 into other buffer -> compute k.
// C[M,*](ldc) = rowscale * (A[M,K] @ W + bias), opt ReLU. Grouped-N for QKV.
// ---------------------------------------------------------------------------
#define SA_STRIDE 20    // 80B rows (16B-aligned, conflict-free frags)
#define SB_STRIDE 136   // 544B rows (16B-aligned, conflict-free frags)

__device__ __forceinline__ float to_tf32(float x) {
    float r;
    asm("cvt.rna.tf32.f32 %0, %1;" : "=f"(r) : "f"(x));
    return r;
}

#define CPA(dst, src, sz) \
    asm volatile("cp.async.ca.shared.global [%0], [%1], 16, %2;\n" \
                 :: "r"(dst), "l"(src), "r"(sz))

template<int WMW>
__global__ __launch_bounds__(256) void gemm_tf32(
    const float* __restrict__ A, const float* __restrict__ Wp,
    const float* __restrict__ biasp, const float* __restrict__ rowscale,
    float* __restrict__ Cp,
    int M, int K, int ldc, int relu,
    int Ninner, long wgs, long bgs, long cgs)
{
    constexpr int WNW = 8 / WMW;          // warps along N
    constexpr int BMt = WMW * 32;         // 128 or 64
    constexpr int NI  = 128 / (WNW * 8);  // n-frags per warp
    constexpr int AV  = BMt / 64;         // A cp.async per thread

    __shared__ __align__(16) float sA[2][BMt * SA_STRIDE];
    __shared__ __align__(16) float sB[2][16 * SB_STRIDE];

    int tid  = threadIdx.x;
    int wid  = tid >> 5;
    int lane = tid & 31;
    int wm = wid / WNW;
    int wn = wid % WNW;
    int g  = lane >> 2;
    int tg = lane & 3;

    int m0 = blockIdx.y * BMt;
    int n0 = blockIdx.x * 128;
    int grp = n0 / Ninner;
    int nl  = n0 - grp * Ninner;
    const float* W    = Wp    + (size_t)grp * wgs;
    const float* bias = biasp + (size_t)grp * bgs;
    float*       C    = Cp    + (size_t)grp * cgs;

    float acc[2][NI][4];
    #pragma unroll
    for (int mi = 0; mi < 2; mi++)
        #pragma unroll
        for (int ni = 0; ni < NI; ni++)
            #pragma unroll
            for (int r = 0; r < 4; r++) acc[mi][ni][r] = 0.f;

    int ntiles = K >> 4;

    // prologue: issue tile 0 into buffer 0
    {
        #pragma unroll
        for (int r = 0; r < AV; r++) {
            int i = tid + r * 256;
            int row = i >> 2, c4 = (i & 3) * 4;
            unsigned dst = (unsigned)__cvta_generic_to_shared(&sA[0][row * SA_STRIDE + c4]);
            const float* src = A + (size_t)(m0 + row) * K + c4;
            CPA(dst, src, (m0 + row < M) ? 16 : 0);
        }
        #pragma unroll
        for (int r = 0; r < 2; r++) {
            int i = tid + r * 256;
            int row = i >> 5, c4 = (i & 31) * 4;
            unsigned dst = (unsigned)__cvta_generic_to_shared(&sB[0][row * SB_STRIDE + c4]);
            const float* src = W + (size_t)row * Ninner + nl + c4;
            CPA(dst, src, 16);
        }
        asm volatile("cp.async.commit_group;\n");
    }

    for (int kt = 0; kt < ntiles; kt++) {
        int cur = kt & 1;
        asm volatile("cp.async.wait_group 0;\n");
        __syncthreads();
        // issue next tile into the other buffer (overlaps with compute below)
        if (kt + 1 < ntiles) {
            int nxt = cur ^ 1;
            int kof = (kt + 1) * 16;
            #pragma unroll
            for (int r = 0; r < AV; r++) {
                int i = tid + r * 256;
                int row = i >> 2, c4 = (i & 3) * 4;
                unsigned dst = (unsigned)__cvta_generic_to_shared(&sA[nxt][row * SA_STRIDE + c4]);
                const float* src = A + (size_t)(m0 + row) * K + kof + c4;
                CPA(dst, src, (m0 + row < M) ? 16 : 0);
            }
            #pragma unroll
            for (int r = 0; r < 2; r++) {
                int i = tid + r * 256;
                int row = i >> 5, c4 = (i & 31) * 4;
                unsigned dst = (unsigned)__cvta_generic_to_shared(&sB[nxt][row * SB_STRIDE + c4]);
                const float* src = W + (size_t)(kof + row) * Ninner + nl + c4;
                CPA(dst, src, 16);
            }
            asm volatile("cp.async.commit_group;\n");
        }

        const float* cA = sA[cur];
        const float* cB = sB[cur];
        #pragma unroll
        for (int ks = 0; ks < 16; ks += 8) {
            unsigned af[2][4];
            #pragma unroll
            for (int mi = 0; mi < 2; mi++) {
                int bm = wm * 32 + mi * 16;
                af[mi][0] = __float_as_uint(to_tf32(cA[(bm + g    ) * SA_STRIDE + ks + tg    ]));
                af[mi][1] = __float_as_uint(to_tf32(cA[(bm + g + 8) * SA_STRIDE + ks + tg    ]));
                af[mi][2] = __float_as_uint(to_tf32(cA[(bm + g    ) * SA_STRIDE + ks + tg + 4]));
                af[mi][3] = __float_as_uint(to_tf32(cA[(bm + g + 8) * SA_STRIDE + ks + tg + 4]));
            }
            unsigned bf[NI][2];
            #pragma unroll
            for (int ni = 0; ni < NI; ni++) {
                int bn = wn * (NI * 8) + ni * 8 + g;
                bf[ni][0] = __float_as_uint(to_tf32(cB[(ks + tg    ) * SB_STRIDE + bn]));
                bf[ni][1] = __float_as_uint(to_tf32(cB[(ks + tg + 4) * SB_STRIDE + bn]));
            }
            #pragma unroll
            for (int mi = 0; mi < 2; mi++)
                #pragma unroll
                for (int ni = 0; ni < NI; ni++) {
                    float* c = acc[mi][ni];
                    asm volatile(
                        "mma.sync.aligned.m16n8k8.row.col.f32.tf32.tf32.f32 "
                        "{%0,%1,%2,%3}, {%4,%5,%6,%7}, {%8,%9}, {%0,%1,%2,%3};\n"
                        : "+f"(c[0]), "+f"(c[1]), "+f"(c[2]), "+f"(c[3])
                        : "r"(af[mi][0]), "r"(af[mi][1]), "r"(af[mi][2]), "r"(af[mi][3]),
                          "r"(bf[ni][0]), "r"(bf[ni][1]));
                }
        }
        // no trailing barrier: next iteration's wait+sync protects buffer reuse
        __syncthreads();
    }

    // epilogue
    #pragma unroll
    for (int mi = 0; mi < 2; mi++) {
        int r0 = m0 + wm * 32 + mi * 16 + g;
        int r1 = r0 + 8;
        float rs0 = 1.f, rs1 = 1.f;
        if (rowscale) {
            if (r0 < M) rs0 = rowscale[r0];
            if (r1 < M) rs1 = rowscale[r1];
        }
        #pragma unroll
        for (int ni = 0; ni < NI; ni++) {
            int cc = wn * (NI * 8) + ni * 8 + 2 * tg;
            float b0 = bias[nl + cc], b1 = bias[nl + cc + 1];
            float v0 = (acc[mi][ni][0] + b0) * rs0;
            float v1 = (acc[mi][ni][1] + b1) * rs0;
            float v2 = (acc[mi][ni][2] + b0) * rs1;
            float v3 = (acc[mi][ni][3] + b1) * rs1;
            if (relu) {
                v0 = fmaxf(v0, 0.f); v1 = fmaxf(v1, 0.f);
                v2 = fmaxf(v2, 0.f); v3 = fmaxf(v3, 0.f);
            }
            if (r0 < M) { C[(size_t)r0 * ldc + nl + cc] = v0; C[(size_t)r0 * ldc + nl + cc + 1] = v1; }
            if (r1 < M) { C[(size_t)r1 * ldc + nl + cc] = v2; C[(size_t)r1 * ldc + nl + cc + 1] = v3; }
        }
    }
}

// ---------------------------------------------------------------------------
// Tiled attention (conflict-free scores), unchanged.
// ---------------------------------------------------------------------------
#define KV_STRIDE 68
#define Q_STRIDE  68
__global__ __launch_bounds__(128) void attn_tiled(
    const float* __restrict__ Q, const float* __restrict__ Kt,
    const float* __restrict__ Vt, const float* __restrict__ mask,
    int mask_mode, float* __restrict__ Out, float* __restrict__ attn_save,
    const float* __restrict__ V2, float* __restrict__ Out2,
    int Sq, int Skv)
{
    int nqt = (Sq + 15) >> 4;
    int qt = blockIdx.x % nqt;
    int h  = (blockIdx.x / nqt) % H_;
    int b  = blockIdx.x / (nqt * H_);
    int i0 = qt * 16;
    int tid = threadIdx.x;
    int wid = tid >> 5;
    int lane = tid & 31;

    __shared__ __align__(16) float sQ[16][Q_STRIDE];
    __shared__ __align__(16) float sS[16][LIN_ + 8];
    __shared__ __align__(16) float sKV[64][KV_STRIDE];

    #pragma unroll
    for (int r = 0; r < 2; r++) {
        int i = tid + r * 128;
        int row = i >> 4, c4 = (i & 15) * 4;
        float4 v = make_float4(0.f, 0.f, 0.f, 0.f);
        if (i0 + row < Sq)
            v = *(const float4*)(Q + (size_t)(b * Sq + i0 + row) * D_ + h * DEPTH_ + c4);
        *(float4*)(&sQ[row][c4]) = v;
    }
    __syncthreads();

    int nchunks = (Skv + 63) >> 6;
    int myq = tid >> 3;
    int jt  = tid & 7;

    for (int jc = 0; jc < nchunks; jc++) {
        int jbase = jc * 64;
        #pragma unroll
        for (int r = 0; r < 8; r++) {
            int i = tid + r * 128;
            int row = i >> 4, c4 = (i & 15) * 4;
            float4 v = make_float4(0.f, 0.f, 0.f, 0.f);
            if (jbase + row < Skv)
                v = *(const float4*)(Kt + (size_t)(b * Skv + jbase + row) * D_ + h * DEPTH_ + c4);
            *(float4*)(&sKV[row][c4]) = v;
        }
        __syncthreads();
        float qacc[8];
        #pragma unroll
        for (int jj = 0; jj < 8; jj++) qacc[jj] = 0.f;
        #pragma unroll 4
        for (int d = 0; d < 64; d++) {
            float qd = sQ[myq][d];
            #pragma unroll
            for (int jj = 0; jj < 8; jj++)
                qacc[jj] += qd * sKV[jt + 8 * jj][d];
        }
        int iq = i0 + myq; if (iq >= Sq) iq = Sq - 1;
        #pragma unroll
        for (int jj = 0; jj < 8; jj++) {
            int j = jbase + jt + 8 * jj;
            if (j < Skv) {
                float mv = (mask_mode == 1)
                    ? mask[((size_t)b * Sq + iq) * Skv + j]
                    : mask[(size_t)b * Skv + j];
                sS[myq][j] = qacc[jj] * 0.125f + mv * -1e9f;
            }
        }
        __syncthreads();
    }

    for (int q = wid; q < 16; q += 4) {
        float mx = -INFINITY;
        for (int j = lane; j < Skv; j += 32) mx = fmaxf(mx, sS[q][j]);
        #pragma unroll
        for (int o = 16; o > 0; o >>= 1)
            mx = fmaxf(mx, __shfl_xor_sync(0xffffffff, mx, o));
        float sum = 0.f;
        for (int j = lane; j < Skv; j += 32) {
            float e = expf(sS[q][j] - mx);
            sS[q][j] = e;
            sum += e;
        }
        #pragma unroll
        for (int o = 16; o > 0; o >>= 1)
            sum += __shfl_xor_sync(0xffffffff, sum, o);
        float inv = 1.f / sum;
        for (int j = lane; j < Skv; j += 32) sS[q][j] *= inv;
    }
    __syncthreads();

    if (attn_save && i0 + myq < Sq) {
        size_t base = (((size_t)(b * H_ + h) * Sq) + i0 + myq) * Skv;
        for (int j = jt; j < Skv; j += 8)
            attn_save[base + j] = sS[myq][j];
    }

    int d8 = jt * 8;
    float acc[8], acc2[8];
    #pragma unroll
    for (int r = 0; r < 8; r++) { acc[r] = 0.f; acc2[r] = 0.f; }

    for (int jc = 0; jc < nchunks; jc++) {
        int jbase = jc * 64;
        int jn = Skv - jbase; if (jn > 64) jn = 64;
        __syncthreads();
        #pragma unroll
        for (int r = 0; r < 8; r++) {
            int i = tid + r * 128;
            int row = i >> 4, c4 = (i & 15) * 4;
            float4 v = make_float4(0.f, 0.f, 0.f, 0.f);
            if (jbase + row < Skv)
                v = *(const float4*)(Vt + (size_t)(b * Skv + jbase + row) * D_ + h * DEPTH_ + c4);
            *(float4*)(&sKV[row][c4]) = v;
        }
        __syncthreads();
        for (int jj = 0; jj < jn; jj++) {
            float p = sS[myq][jbase + jj];
            #pragma unroll
            for (int dd = 0; dd < 8; dd++)
                acc[dd] += p * sKV[jj][d8 + dd];
        }
        if (V2) {
            __syncthreads();
            #pragma unroll
            for (int r = 0; r < 8; r++) {
                int i = tid + r * 128;
                int row = i >> 4, c4 = (i & 15) * 4;
                float4 v = make_float4(0.f, 0.f, 0.f, 0.f);
                if (jbase + row < Skv)
                    v = *(const float4*)(V2 + (size_t)(b * Skv + jbase + row) * D_ + h * DEPTH_ + c4);
                *(float4*)(&sKV[row][c4]) = v;
            }
            __syncthreads();
            for (int jj = 0; jj < jn; jj++) {
                float p = sS[myq][jbase + jj];
                #pragma unroll
                for (int dd = 0; dd < 8; dd++)
                    acc2[dd] += p * sKV[jj][d8 + dd];
            }
        }
    }
    if (i0 + myq < Sq) {
        size_t base = (size_t)(b * Sq + i0 + myq) * D_ + h * DEPTH_ + d8;
        #pragma unroll
        for (int dd = 0; dd < 8; dd++) Out[base + dd] = acc[dd];
        if (Out2)
            #pragma unroll
            for (int dd = 0; dd < 8; dd++) Out2[base + dd] = acc2[dd];
    }
}

// ---------------------------------------------------------------------------
__global__ __launch_bounds__(128) void add_ln(
    const float* __restrict__ X, const float* __restrict__ A,
    const float* __restrict__ g, const float* __restrict__ beta,
    float* __restrict__ Y)
{
    int row = blockIdx.x;
    int tid = threadIdx.x;
    __shared__ float red[128];
    size_t base = (size_t)row * D_;
    float v[4];
    float s = 0.f;
    #pragma unroll
    for (int k = 0; k < 4; k++) {
        v[k] = X[base + tid + k * 128] + A[base + tid + k * 128];
        s += v[k];
    }
    red[tid] = s; __syncthreads();
    for (int st = 64; st > 0; st >>= 1) {
        if (tid < st) red[tid] += red[tid + st];
        __syncthreads();
    }
    float mu = red[0] * (1.f / D_);
    __syncthreads();
    float vs = 0.f;
    #pragma unroll
    for (int k = 0; k < 4; k++) { float d = v[k] - mu; vs += d * d; }
    red[tid] = vs; __syncthreads();
    for (int st = 64; st > 0; st >>= 1) {
        if (tid < st) red[tid] += red[tid + st];
        __syncthreads();
    }
    float inv = rsqrtf(red[0] * (1.f / D_) + 1e-6f);
    #pragma unroll
    for (int k = 0; k < 4; k++) {
        int c = tid + k * 128;
        Y[base + c] = (v[k] - mu) * inv * g[c] + beta[c];
    }
}

__global__ __launch_bounds__(128) void pgen_kernel(
    const float* __restrict__ ctx, const float* __restrict__ dec,
    const float* __restrict__ emb, const float* __restrict__ ptrw,
    const float* __restrict__ ptrb, float* __restrict__ pg)
{
    int row = blockIdx.x;
    int tid = threadIdx.x;
    __shared__ float red[128];
    size_t base = (size_t)row * D_;
    float s = 0.f;
    for (int c = tid; c < D_; c += 128)
        s += ctx[base + c] * ptrw[c] + dec[base + c] * ptrw[D_ + c]
           + emb[base + c] * ptrw[2 * D_ + c];
    red[tid] = s; __syncthreads();
    for (int st = 64; st > 0; st >>= 1) {
        if (tid < st) red[tid] += red[tid + st];
        __syncthreads();
    }
    if (tid == 0) {
        float z = red[0] + ptrb[0] + ptrb[1] + ptrb[2];
        pg[row] = 1.f / (1.f + expf(-z));
    }
}

__global__ __launch_bounds__(128) void attn_mean_kernel(
    const float* __restrict__ block2, float* __restrict__ out2)
{
    int row = blockIdx.x;
    int b = row / T_, t = row % T_;
    for (int l = threadIdx.x; l < LIN_; l += 128) {
        float s = 0.f;
        #pragma unroll
        for (int h = 0; h < H_; h++)
            s += block2[((size_t)(b * H_ + h) * T_ + t) * LIN_ + l];
        out2[(size_t)row * LIN_ + l] = s * 0.125f;
    }
}

__global__ void zero_tail_kernel(float* __restrict__ out) {
    int idx = blockIdx.x * blockDim.x + threadIdx.x;
    if (idx >= B_ * T_ * 100) return;
    int row = idx / 100;
    int t   = idx % 100;
    out[(size_t)row * VEXT_ + V_ + t] = 0.f;
}

__global__ void scatter_kernel(float* __restrict__ out,
                               const float* __restrict__ am,
                               const float* __restrict__ pg,
                               const int* __restrict__ ext)
{
    int idx = blockIdx.x * blockDim.x + threadIdx.x;
    if (idx >= B_ * T_ * LIN_) return;
    int l = idx % LIN_;
    int row = idx / LIN_;
    int b = row / T_;
    float q = 1.f - pg[row];
    atomicAdd(&out[(size_t)row * VEXT_ + ext[(size_t)b * LIN_ + l]],
              q * am[(size_t)row * LIN_ + l]);
}

// ---------------------------------------------------------------------------
static inline void gemmN(const float* A, const float* W, const float* bias,
                         const float* rs, float* C, int M, int Ntot, int K,
                         int ldc, int relu,
                         int Ninner, long wgs, long bgs, long cgs) {
    if (M > 2048) {
        dim3 grid(Ntot / 128, (M + 127) / 128);
        gemm_tf32<4><<<grid, 256>>>(A, W, bias, rs, C, M, K, ldc, relu,
                                    Ninner, wgs, bgs, cgs);
    } else {
        dim3 grid(Ntot / 128, (M + 63) / 64);
        gemm_tf32<2><<<grid, 256>>>(A, W, bias, rs, C, M, K, ldc, relu,
                                    Ninner, wgs, bgs, cgs);
    }
}
static inline void gemm(const float* A, const float* W, const float* bias,
                        const float* rs, float* C, int M, int N, int K,
                        int ldc, int relu) {
    gemmN(A, W, bias, rs, C, M, N, K, ldc, relu, N, 0, 0, 0);
}

extern "C" void kernel_launch(void* const* d_in, const int* in_sizes, int n_in,
                              void* d_out, int out_size) {
    const int*   inp     = (const int*)d_in[0];
    const int*   tar     = (const int*)d_in[1];
    const int*   ext     = (const int*)d_in[2];
    const float* enc_pad = (const float*)d_in[3];
    const float* look    = (const float*)d_in[4];
    const float* dec_pad = (const float*)d_in[5];
    int o = (in_sizes[6] <= 4) ? 7 : 6;
    const float* emb_enc = (const float*)d_in[o + 0];
    const float* emb_dec = (const float*)d_in[o + 1];
    const float* eaw  = (const float*)d_in[o + 2];
    const float* eab  = (const float*)d_in[o + 3];
    const float* ew1  = (const float*)d_in[o + 4];
    const float* eb1  = (const float*)d_in[o + 5];
    const float* ew2  = (const float*)d_in[o + 6];
    const float* eb2  = (const float*)d_in[o + 7];
    const float* elng = (const float*)d_in[o + 8];
    const float* elnb = (const float*)d_in[o + 9];
    const float* daw  = (const float*)d_in[o + 10];
    const float* dab  = (const float*)d_in[o + 11];
    const float* dw1  = (const float*)d_in[o + 12];
    const float* db1  = (const float*)d_in[o + 13];
    const float* dw2  = (const float*)d_in[o + 14];
    const float* db2  = (const float*)d_in[o + 15];
    const float* dlng = (const float*)d_in[o + 16];
    const float* dlnb = (const float*)d_in[o + 17];
    const float* ptrw = (const float*)d_in[o + 18];
    const float* ptrb = (const float*)d_in[o + 19];
    const float* finw = (const float*)d_in[o + 20];
    const float* finb = (const float*)d_in[o + 21];
    float* out = (float*)d_out;

    float *pe, *encx, *qkv, *attno, *tmp, *ffn, *decx, *o1buf,
          *embedr, *block2, *ctx, *pg;
    cudaGetSymbolAddress((void**)&pe,     g_pe);
    cudaGetSymbolAddress((void**)&encx,   g_encx);
    cudaGetSymbolAddress((void**)&qkv,    g_qkv);
    cudaGetSymbolAddress((void**)&attno,  g_attno);
    cudaGetSymbolAddress((void**)&tmp,    g_tmp);
    cudaGetSymbolAddress((void**)&ffn,    g_ffn);
    cudaGetSymbolAddress((void**)&decx,   g_decx);
    cudaGetSymbolAddress((void**)&o1buf,  g_o1);
    cudaGetSymbolAddress((void**)&embedr, g_embed);
    cudaGetSymbolAddress((void**)&block2, g_block2);
    cudaGetSymbolAddress((void**)&ctx,    g_ctx);
    cudaGetSymbolAddress((void**)&pg,     g_pg);

    float* q = qkv;
    float* k = qkv + QKV_SZ;
    float* v = qkv + 2 * QKV_SZ;

    const int ME = B_ * LIN_;  // 6400
    const int MD = B_ * T_;    // 1600
    const long DD = (long)D_ * D_;

    pe_kernel<<<(LIN_ * D_ + 255) / 256, 256>>>(pe);
    embed_kernel<<<(ME * D_ + 255) / 256, 256>>>(inp, emb_enc, pe, encx,
                                                 nullptr, LIN_, ME * D_);
    embed_kernel<<<(MD * D_ + 255) / 256, 256>>>(tar, emb_dec, pe, decx,
                                                 embedr, T_, MD * D_);

    // ----- encoder -----
    for (int i = 0; i < L_; i++) {
        const float* w  = eaw + (size_t)i * 4 * DD;
        const float* bb = eab + (size_t)i * 4 * D_;
        gemmN(encx, w, bb, nullptr, q, ME, 3 * D_, D_, D_, 0,
              D_, DD, D_, QKV_SZ);
        attn_tiled<<<B_ * H_ * ((LIN_ + 15) / 16), 128>>>(
            q, k, v, enc_pad, 0, attno, nullptr, nullptr, nullptr, LIN_, LIN_);
        gemm(attno, w + 3 * DD, bb + 3 * D_, nullptr, tmp, ME, D_, D_, D_, 0);
        add_ln<<<ME, 128>>>(encx, tmp, elng + (size_t)(i * 2 + 0) * D_,
                            elnb + (size_t)(i * 2 + 0) * D_, encx);
        gemm(encx, ew1 + (size_t)i * D_ * DFF_, eb1 + (size_t)i * DFF_,
             nullptr, ffn, ME, DFF_, D_, DFF_, 1);
        gemm(ffn, ew2 + (size_t)i * DFF_ * D_, eb2 + (size_t)i * D_,
             nullptr, tmp, ME, D_, DFF_, D_, 0);
        add_ln<<<ME, 128>>>(encx, tmp, elng + (size_t)(i * 2 + 1) * D_,
                            elnb + (size_t)(i * 2 + 1) * D_, encx);
    }

    // ----- decoder: only layer L-1 affects outputs -----
    {
        const int i = L_ - 1;
        const float* w0 = daw + (size_t)(i * 2 + 0) * 4 * DD;
        const float* b0 = dab + (size_t)(i * 2 + 0) * 4 * D_;
        gemmN(decx, w0, b0, nullptr, q, MD, 3 * D_, D_, D_, 0,
              D_, DD, D_, QKV_SZ);
        attn_tiled<<<B_ * H_ * ((T_ + 15) / 16), 128>>>(
            q, k, v, look, 1, attno, nullptr, nullptr, nullptr, T_, T_);
        gemm(attno, w0 + 3 * DD, b0 + 3 * D_, nullptr, tmp, MD, D_, D_, D_, 0);
        add_ln<<<MD, 128>>>(decx, tmp, dlng + (size_t)(i * 3 + 0) * D_,
                            dlnb + (size_t)(i * 3 + 0) * D_, o1buf);
        // cross-attention; fuses context = P @ enc_heads
        const float* w1 = daw + (size_t)(i * 2 + 1) * 4 * DD;
        const float* b1 = dab + (size_t)(i * 2 + 1) * 4 * D_;
        gemm(o1buf, w1, b1, nullptr, q, MD, D_, D_, D_, 0);
        gemmN(encx, w1 + DD, b1 + D_, nullptr, k, ME, 2 * D_, D_, D_, 0,
              D_, DD, D_, QKV_SZ);
        attn_tiled<<<B_ * H_ * ((T_ + 15) / 16), 128>>>(
            q, k, v, dec_pad, 0, attno, block2, encx, ctx, T_, LIN_);
        gemm(attno, w1 + 3 * DD, b1 + 3 * D_, nullptr, tmp, MD, D_, D_, D_, 0);
        add_ln<<<MD, 128>>>(o1buf, tmp, dlng + (size_t)(i * 3 + 1) * D_,
                            dlnb + (size_t)(i * 3 + 1) * D_, o1buf);
        gemm(o1buf, dw1 + (size_t)i * D_ * DFF_, db1 + (size_t)i * DFF_,
             nullptr, ffn, MD, DFF_, D_, DFF_, 1);
        gemm(ffn, dw2 + (size_t)i * DFF_ * D_, db2 + (size_t)i * D_,
             nullptr, tmp, MD, D_, DFF_, D_, 0);
        add_ln<<<MD, 128>>>(o1buf, tmp, dlng + (size_t)(i * 3 + 2) * D_,
                            dlnb + (size_t)(i * 3 + 2) * D_, decx);
    }

    // ----- pointer-generator prob, head with fused p*logits -----
    pgen_kernel<<<MD, 128>>>(ctx, decx, embedr, ptrw, ptrb, pg);
    gemm(decx, finw, finb, pg, out, MD, V_, D_, VEXT_, 0);
    zero_tail_kernel<<<(MD * 100 + 255) / 256, 256>>>(out);

    float* out2 = out + (size_t)MD * VEXT_;
    attn_mean_kernel<<<MD, 128>>>(block2, out2);
    scatter_kernel<<<(B_ * T_ * LIN_ + 255) / 256, 256>>>(out, out2, pg, ext);
}

// round 15
// speedup vs baseline: 1.7073x; 1.1216x over previous
#include <cuda_runtime.h>
#include <cuda_bf16.h>
#include <math.h>

#define V_  32000
#define D_  512
#define H_  8
#define DFF_ 2048
#define L_  2
#define B_  16
#define LIN_ 400
#define T_  100
#define DEPTH_ 64
#define VEXT_ 32100
#define SQRT_D 22.627416997969522f
#define QKV_SZ (B_*LIN_*D_)
#define DD_ 262144              // D*D

// rounded-weight scratch mirror offsets (floats)
#define O_EAW  0
#define O_EW1  2097152
#define O_EW2  4194304
#define O_DAW  6291456
#define O_DW1  10485760
#define O_DW2  12582912
#define O_FINW 14680064
#define WTF_TOTAL 31064064

// ---------------------------------------------------------------------------
// Scratch
// ---------------------------------------------------------------------------
__device__ __align__(16) float g_pe   [LIN_ * D_];
__device__ __align__(16) float g_encx [B_*LIN_ * D_];
__device__ __align__(16) float g_qkv  [3 * QKV_SZ];
__device__ __align__(16) float g_attno[B_*LIN_ * D_];
__device__ __align__(16) float g_tmp  [B_*LIN_ * D_];
__device__ __align__(16) float g_ffn  [B_*LIN_ * DFF_];
__device__ __align__(16) float g_decx [B_*T_ * D_];
__device__ __align__(16) float g_o1   [B_*T_ * D_];
__device__ __align__(16) float g_embed[B_*T_ * D_];
__device__ __align__(16) float g_block2[B_*H_*T_*LIN_];
__device__ __align__(16) float g_ctx  [B_*T_ * D_];
__device__ __align__(16) float g_wtf  [WTF_TOTAL];
__device__ float g_pg   [B_*T_];

__device__ __forceinline__ float to_tf32(float x) {
    float r;
    asm("cvt.rna.tf32.f32 %0, %1;" : "=f"(r) : "f"(x));
    return r;
}

// bulk tf32 rounding (float4), n divisible by 4
__global__ void round_bulk(const float* __restrict__ in,
                           float* __restrict__ out, int n4) {
    int i = blockIdx.x * blockDim.x + threadIdx.x;
    if (i >= n4) return;
    float4 v = ((const float4*)in)[i];
    v.x = to_tf32(v.x); v.y = to_tf32(v.y);
    v.z = to_tf32(v.z); v.w = to_tf32(v.w);
    ((float4*)out)[i] = v;
}

// ---------------------------------------------------------------------------
__global__ void pe_kernel(float* pe) {
    int idx = blockIdx.x * blockDim.x + threadIdx.x;
    if (idx >= LIN_ * D_) return;
    int pos = idx >> 9;
    int d   = idx & (D_ - 1);
    float k2 = (float)(2 * (d >> 1)) * (1.0f / 512.0f);
    float rate = exp2f(-k2 * 13.287712379549449f);   // log2(10000)
    float ang = (float)pos * rate;
    pe[idx] = (d & 1) ? cosf(ang) : sinf(ang);
}

// embedding gather; x output tf32-rounded (feeds GEMM A)
__global__ void embed_kernel(const int* __restrict__ tok,
                             const float* __restrict__ emb,
                             const float* __restrict__ pe,
                             float* __restrict__ x,
                             float* __restrict__ raw,
                             int S, int count) {
    int idx = blockIdx.x * blockDim.x + threadIdx.x;
    if (idx >= count) return;
    int d  = idx & (D_ - 1);
    int bs = idx >> 9;
    int s  = bs % S;
    float e = emb[(size_t)tok[bs] * D_ + d];
    if (raw) raw[idx] = e;
    x[idx] = to_tf32(e * SQRT_D + pe[s * D_ + d]);
}

// ---------------------------------------------------------------------------
// TF32 tensor-core GEMM, cp.async single-barrier pipeline.
// Operands assumed PRE-ROUNDED to tf32 (weights via round_bulk, activations
// via producer epilogues) -> no cvt in mainloop.
// roundC: round output to tf32 (when C feeds another GEMM's A).
// ---------------------------------------------------------------------------
#define SA_STRIDE 20
#define SB_STRIDE 136

#define CPA(dst, src, sz) \
    asm volatile("cp.async.ca.shared.global [%0], [%1], 16, %2;\n" \
                 :: "r"(dst), "l"(src), "r"(sz))

template<int WMW>
__global__ __launch_bounds__(256) void gemm_tf32(
    const float* __restrict__ A, const float* __restrict__ Wp,
    const float* __restrict__ biasp, const float* __restrict__ rowscale,
    float* __restrict__ Cp,
    int M, int K, int ldc, int relu, int roundC,
    int Ninner, long wgs, long bgs, long cgs)
{
    constexpr int WNW = 8 / WMW;
    constexpr int BMt = WMW * 32;
    constexpr int NI  = 128 / (WNW * 8);
    constexpr int AV  = BMt / 64;

    __shared__ __align__(16) float sA[2][BMt * SA_STRIDE];
    __shared__ __align__(16) float sB[2][16 * SB_STRIDE];

    int tid  = threadIdx.x;
    int wid  = tid >> 5;
    int lane = tid & 31;
    int wm = wid / WNW;
    int wn = wid % WNW;
    int g  = lane >> 2;
    int tg = lane & 3;

    int m0 = blockIdx.y * BMt;
    int n0 = blockIdx.x * 128;
    int grp = n0 / Ninner;
    int nl  = n0 - grp * Ninner;
    const float* W    = Wp    + (size_t)grp * wgs;
    const float* bias = biasp + (size_t)grp * bgs;
    float*       C    = Cp    + (size_t)grp * cgs;

    float acc[2][NI][4];
    #pragma unroll
    for (int mi = 0; mi < 2; mi++)
        #pragma unroll
        for (int ni = 0; ni < NI; ni++)
            #pragma unroll
            for (int r = 0; r < 4; r++) acc[mi][ni][r] = 0.f;

    int ntiles = K >> 4;

    {
        #pragma unroll
        for (int r = 0; r < AV; r++) {
            int i = tid + r * 256;
            int row = i >> 2, c4 = (i & 3) * 4;
            unsigned dst = (unsigned)__cvta_generic_to_shared(&sA[0][row * SA_STRIDE + c4]);
            const float* src = A + (size_t)(m0 + row) * K + c4;
            CPA(dst, src, (m0 + row < M) ? 16 : 0);
        }
        #pragma unroll
        for (int r = 0; r < 2; r++) {
            int i = tid + r * 256;
            int row = i >> 5, c4 = (i & 31) * 4;
            unsigned dst = (unsigned)__cvta_generic_to_shared(&sB[0][row * SB_STRIDE + c4]);
            const float* src = W + (size_t)row * Ninner + nl + c4;
            CPA(dst, src, 16);
        }
        asm volatile("cp.async.commit_group;\n");
    }

    for (int kt = 0; kt < ntiles; kt++) {
        int cur = kt & 1;
        asm volatile("cp.async.wait_group 0;\n");
        __syncthreads();
        if (kt + 1 < ntiles) {
            int nxt = cur ^ 1;
            int kof = (kt + 1) * 16;
            #pragma unroll
            for (int r = 0; r < AV; r++) {
                int i = tid + r * 256;
                int row = i >> 2, c4 = (i & 3) * 4;
                unsigned dst = (unsigned)__cvta_generic_to_shared(&sA[nxt][row * SA_STRIDE + c4]);
                const float* src = A + (size_t)(m0 + row) * K + kof + c4;
                CPA(dst, src, (m0 + row < M) ? 16 : 0);
            }
            #pragma unroll
            for (int r = 0; r < 2; r++) {
                int i = tid + r * 256;
                int row = i >> 5, c4 = (i & 31) * 4;
                unsigned dst = (unsigned)__cvta_generic_to_shared(&sB[nxt][row * SB_STRIDE + c4]);
                const float* src = W + (size_t)(kof + row) * Ninner + nl + c4;
                CPA(dst, src, 16);
            }
            asm volatile("cp.async.commit_group;\n");
        }

        const float* cA = sA[cur];
        const float* cB = sB[cur];
        #pragma unroll
        for (int ks = 0; ks < 16; ks += 8) {
            unsigned af[2][4];
            #pragma unroll
            for (int mi = 0; mi < 2; mi++) {
                int bm = wm * 32 + mi * 16;
                af[mi][0] = __float_as_uint(cA[(bm + g    ) * SA_STRIDE + ks + tg    ]);
                af[mi][1] = __float_as_uint(cA[(bm + g + 8) * SA_STRIDE + ks + tg    ]);
                af[mi][2] = __float_as_uint(cA[(bm + g    ) * SA_STRIDE + ks + tg + 4]);
                af[mi][3] = __float_as_uint(cA[(bm + g + 8) * SA_STRIDE + ks + tg + 4]);
            }
            unsigned bf[NI][2];
            #pragma unroll
            for (int ni = 0; ni < NI; ni++) {
                int bn = wn * (NI * 8) + ni * 8 + g;
                bf[ni][0] = __float_as_uint(cB[(ks + tg    ) * SB_STRIDE + bn]);
                bf[ni][1] = __float_as_uint(cB[(ks + tg + 4) * SB_STRIDE + bn]);
            }
            #pragma unroll
            for (int mi = 0; mi < 2; mi++)
                #pragma unroll
                for (int ni = 0; ni < NI; ni++) {
                    float* c = acc[mi][ni];
                    asm volatile(
                        "mma.sync.aligned.m16n8k8.row.col.f32.tf32.tf32.f32 "
                        "{%0,%1,%2,%3}, {%4,%5,%6,%7}, {%8,%9}, {%0,%1,%2,%3};\n"
                        : "+f"(c[0]), "+f"(c[1]), "+f"(c[2]), "+f"(c[3])
                        : "r"(af[mi][0]), "r"(af[mi][1]), "r"(af[mi][2]), "r"(af[mi][3]),
                          "r"(bf[ni][0]), "r"(bf[ni][1]));
                }
        }
        __syncthreads();
    }

    #pragma unroll
    for (int mi = 0; mi < 2; mi++) {
        int r0 = m0 + wm * 32 + mi * 16 + g;
        int r1 = r0 + 8;
        float rs0 = 1.f, rs1 = 1.f;
        if (rowscale) {
            if (r0 < M) rs0 = rowscale[r0];
            if (r1 < M) rs1 = rowscale[r1];
        }
        #pragma unroll
        for (int ni = 0; ni < NI; ni++) {
            int cc = wn * (NI * 8) + ni * 8 + 2 * tg;
            float b0 = bias[nl + cc], b1 = bias[nl + cc + 1];
            float v0 = (acc[mi][ni][0] + b0) * rs0;
            float v1 = (acc[mi][ni][1] + b1) * rs0;
            float v2 = (acc[mi][ni][2] + b0) * rs1;
            float v3 = (acc[mi][ni][3] + b1) * rs1;
            if (relu) {
                v0 = fmaxf(v0, 0.f); v1 = fmaxf(v1, 0.f);
                v2 = fmaxf(v2, 0.f); v3 = fmaxf(v3, 0.f);
            }
            if (roundC) {
                v0 = to_tf32(v0); v1 = to_tf32(v1);
                v2 = to_tf32(v2); v3 = to_tf32(v3);
            }
            if (r0 < M) { C[(size_t)r0 * ldc + nl + cc] = v0; C[(size_t)r0 * ldc + nl + cc + 1] = v1; }
            if (r1 < M) { C[(size_t)r1 * ldc + nl + cc] = v2; C[(size_t)r1 * ldc + nl + cc + 1] = v3; }
        }
    }
}

// ---------------------------------------------------------------------------
// Tiled attention: 32 queries/block, 128 threads, dynamic smem.
// Thread (qg=tid>>3, jt=tid&7) covers q rows {qg, qg+16}:
//   scores: 2q x 8j register block (K/V smem bytes reused 2x)
//   PV:     2q x 8d register block
// Out stores tf32-rounded (feeds GEMM). Out2 (ctx) unrounded.
// ---------------------------------------------------------------------------
#define QT 32
#define KV_STRIDE 68
#define Q_STRIDE  68
#define SS_STRIDE (LIN_ + 8)
#define ATTN_SMEM (QT*Q_STRIDE*4 + QT*SS_STRIDE*4 + 64*KV_STRIDE*4)

__global__ __launch_bounds__(128) void attn_tiled(
    const float* __restrict__ Q, const float* __restrict__ Kt,
    const float* __restrict__ Vt, const float* __restrict__ mask,
    int mask_mode, float* __restrict__ Out, float* __restrict__ attn_save,
    const float* __restrict__ V2, float* __restrict__ Out2,
    int Sq, int Skv)
{
    extern __shared__ __align__(16) float smem[];
    float (*sQ)[Q_STRIDE]  = (float(*)[Q_STRIDE])smem;
    float (*sS)[SS_STRIDE] = (float(*)[SS_STRIDE])(smem + QT * Q_STRIDE);
    float (*sKV)[KV_STRIDE] = (float(*)[KV_STRIDE])(smem + QT * Q_STRIDE + QT * SS_STRIDE);

    int nqt = (Sq + QT - 1) / QT;
    int qt = blockIdx.x % nqt;
    int h  = (blockIdx.x / nqt) % H_;
    int b  = blockIdx.x / (nqt * H_);
    int i0 = qt * QT;
    int tid = threadIdx.x;
    int wid = tid >> 5;
    int lane = tid & 31;

    // load Q tile: 32 rows x 64 cols
    #pragma unroll
    for (int r = 0; r < 4; r++) {
        int i = tid + r * 128;
        int row = i >> 4, c4 = (i & 15) * 4;
        float4 v = make_float4(0.f, 0.f, 0.f, 0.f);
        if (i0 + row < Sq)
            v = *(const float4*)(Q + (size_t)(b * Sq + i0 + row) * D_ + h * DEPTH_ + c4);
        *(float4*)(&sQ[row][c4]) = v;
    }
    __syncthreads();

    int nchunks = (Skv + 63) >> 6;
    int qg = tid >> 3;            // 0..15
    int jt = tid & 7;             // 0..7

    // ----- scores: 2q x 8j register block -----
    for (int jc = 0; jc < nchunks; jc++) {
        int jbase = jc * 64;
        #pragma unroll
        for (int r = 0; r < 8; r++) {
            int i = tid + r * 128;
            int row = i >> 4, c4 = (i & 15) * 4;
            float4 v = make_float4(0.f, 0.f, 0.f, 0.f);
            if (jbase + row < Skv)
                v = *(const float4*)(Kt + (size_t)(b * Skv + jbase + row) * D_ + h * DEPTH_ + c4);
            *(float4*)(&sKV[row][c4]) = v;
        }
        __syncthreads();
        float qa0[8], qa1[8];
        #pragma unroll
        for (int jj = 0; jj < 8; jj++) { qa0[jj] = 0.f; qa1[jj] = 0.f; }
        #pragma unroll 4
        for (int d = 0; d < 64; d++) {
            float q0 = sQ[qg][d];
            float q1 = sQ[qg + 16][d];
            #pragma unroll
            for (int jj = 0; jj < 8; jj++) {
                float kv = sKV[jt + 8 * jj][d];
                qa0[jj] += q0 * kv;
                qa1[jj] += q1 * kv;
            }
        }
        int iq0 = i0 + qg;      if (iq0 >= Sq) iq0 = Sq - 1;
        int iq1 = i0 + qg + 16; if (iq1 >= Sq) iq1 = Sq - 1;
        #pragma unroll
        for (int jj = 0; jj < 8; jj++) {
            int j = jbase + jt + 8 * jj;
            if (j < Skv) {
                float mv0 = (mask_mode == 1)
                    ? mask[((size_t)b * Sq + iq0) * Skv + j]
                    : mask[(size_t)b * Skv + j];
                float mv1 = (mask_mode == 1)
                    ? mask[((size_t)b * Sq + iq1) * Skv + j]
                    : mask[(size_t)b * Skv + j];
                sS[qg][j]      = qa0[jj] * 0.125f + mv0 * -1e9f;
                sS[qg + 16][j] = qa1[jj] * 0.125f + mv1 * -1e9f;
            }
        }
        __syncthreads();
    }

    // ----- softmax: warp w handles rows w, w+4, ... -----
    for (int q = wid; q < QT; q += 4) {
        float mx = -INFINITY;
        for (int j = lane; j < Skv; j += 32) mx = fmaxf(mx, sS[q][j]);
        #pragma unroll
        for (int o = 16; o > 0; o >>= 1)
            mx = fmaxf(mx, __shfl_xor_sync(0xffffffff, mx, o));
        float sum = 0.f;
        for (int j = lane; j < Skv; j += 32) {
            float e = expf(sS[q][j] - mx);
            sS[q][j] = e;
            sum += e;
        }
        #pragma unroll
        for (int o = 16; o > 0; o >>= 1)
            sum += __shfl_xor_sync(0xffffffff, sum, o);
        float inv = 1.f / sum;
        for (int j = lane; j < Skv; j += 32) sS[q][j] *= inv;
    }
    __syncthreads();

    // probs dump
    if (attn_save) {
        if (i0 + qg < Sq) {
            size_t base = (((size_t)(b * H_ + h) * Sq) + i0 + qg) * Skv;
            for (int j = jt; j < Skv; j += 8) attn_save[base + j] = sS[qg][j];
        }
        if (i0 + qg + 16 < Sq) {
            size_t base = (((size_t)(b * H_ + h) * Sq) + i0 + qg + 16) * Skv;
            for (int j = jt; j < Skv; j += 8) attn_save[base + j] = sS[qg + 16][j];
        }
    }

    // ----- PV (and optional P@V2): 2q x 8d register block -----
    int d8 = jt * 8;
    float a0[8], a1[8], c0[8], c1[8];
    #pragma unroll
    for (int r = 0; r < 8; r++) { a0[r] = 0.f; a1[r] = 0.f; c0[r] = 0.f; c1[r] = 0.f; }

    for (int jc = 0; jc < nchunks; jc++) {
        int jbase = jc * 64;
        int jn = Skv - jbase; if (jn > 64) jn = 64;
        __syncthreads();
        #pragma unroll
        for (int r = 0; r < 8; r++) {
            int i = tid + r * 128;
            int row = i >> 4, c4 = (i & 15) * 4;
            float4 v = make_float4(0.f, 0.f, 0.f, 0.f);
            if (jbase + row < Skv)
                v = *(const float4*)(Vt + (size_t)(b * Skv + jbase + row) * D_ + h * DEPTH_ + c4);
            *(float4*)(&sKV[row][c4]) = v;
        }
        __syncthreads();
        for (int jj = 0; jj < jn; jj++) {
            float p0 = sS[qg][jbase + jj];
            float p1 = sS[qg + 16][jbase + jj];
            #pragma unroll
            for (int dd = 0; dd < 8; dd++) {
                float vv = sKV[jj][d8 + dd];
                a0[dd] += p0 * vv;
                a1[dd] += p1 * vv;
            }
        }
        if (V2) {
            __syncthreads();
            #pragma unroll
            for (int r = 0; r < 8; r++) {
                int i = tid + r * 128;
                int row = i >> 4, c4 = (i & 15) * 4;
                float4 v = make_float4(0.f, 0.f, 0.f, 0.f);
                if (jbase + row < Skv)
                    v = *(const float4*)(V2 + (size_t)(b * Skv + jbase + row) * D_ + h * DEPTH_ + c4);
                *(float4*)(&sKV[row][c4]) = v;
            }
            __syncthreads();
            for (int jj = 0; jj < jn; jj++) {
                float p0 = sS[qg][jbase + jj];
                float p1 = sS[qg + 16][jbase + jj];
                #pragma unroll
                for (int dd = 0; dd < 8; dd++) {
                    float vv = sKV[jj][d8 + dd];
                    c0[dd] += p0 * vv;
                    c1[dd] += p1 * vv;
                }
            }
        }
    }
    if (i0 + qg < Sq) {
        size_t base = (size_t)(b * Sq + i0 + qg) * D_ + h * DEPTH_ + d8;
        #pragma unroll
        for (int dd = 0; dd < 8; dd++) Out[base + dd] = to_tf32(a0[dd]);
        if (Out2)
            #pragma unroll
            for (int dd = 0; dd < 8; dd++) Out2[base + dd] = c0[dd];
    }
    if (i0 + qg + 16 < Sq) {
        size_t base = (size_t)(b * Sq + i0 + qg + 16) * D_ + h * DEPTH_ + d8;
        #pragma unroll
        for (int dd = 0; dd < 8; dd++) Out[base + dd] = to_tf32(a1[dd]);
        if (Out2)
            #pragma unroll
            for (int dd = 0; dd < 8; dd++) Out2[base + dd] = c1[dd];
    }
}

// ---------------------------------------------------------------------------
// y = tf32_round(LayerNorm(x + a) * g + beta)  (output feeds GEMM A)
// ---------------------------------------------------------------------------
__global__ __launch_bounds__(128) void add_ln(
    const float* __restrict__ X, const float* __restrict__ A,
    const float* __restrict__ g, const float* __restrict__ beta,
    float* __restrict__ Y)
{
    int row = blockIdx.x;
    int tid = threadIdx.x;
    __shared__ float red[128];
    size_t base = (size_t)row * D_;
    float v[4];
    float s = 0.f;
    #pragma unroll
    for (int k = 0; k < 4; k++) {
        v[k] = X[base + tid + k * 128] + A[base + tid + k * 128];
        s += v[k];
    }
    red[tid] = s; __syncthreads();
    for (int st = 64; st > 0; st >>= 1) {
        if (tid < st) red[tid] += red[tid + st];
        __syncthreads();
    }
    float mu = red[0] * (1.f / D_);
    __syncthreads();
    float vs = 0.f;
    #pragma unroll
    for (int k = 0; k < 4; k++) { float d = v[k] - mu; vs += d * d; }
    red[tid] = vs; __syncthreads();
    for (int st = 64; st > 0; st >>= 1) {
        if (tid < st) red[tid] += red[tid + st];
        __syncthreads();
    }
    float inv = rsqrtf(red[0] * (1.f / D_) + 1e-6f);
    #pragma unroll
    for (int k = 0; k < 4; k++) {
        int c = tid + k * 128;
        Y[base + c] = to_tf32((v[k] - mu) * inv * g[c] + beta[c]);
    }
}

__global__ __launch_bounds__(128) void pgen_kernel(
    const float* __restrict__ ctx, const float* __restrict__ dec,
    const float* __restrict__ emb, const float* __restrict__ ptrw,
    const float* __restrict__ ptrb, float* __restrict__ pg)
{
    int row = blockIdx.x;
    int tid = threadIdx.x;
    __shared__ float red[128];
    size_t base = (size_t)row * D_;
    float s = 0.f;
    for (int c = tid; c < D_; c += 128)
        s += ctx[base + c] * ptrw[c] + dec[base + c] * ptrw[D_ + c]
           + emb[base + c] * ptrw[2 * D_ + c];
    red[tid] = s; __syncthreads();
    for (int st = 64; st > 0; st >>= 1) {
        if (tid < st) red[tid] += red[tid + st];
        __syncthreads();
    }
    if (tid == 0) {
        float z = red[0] + ptrb[0] + ptrb[1] + ptrb[2];
        pg[row] = 1.f / (1.f + expf(-z));
    }
}

__global__ __launch_bounds__(128) void attn_mean_kernel(
    const float* __restrict__ block2, float* __restrict__ out2)
{
    int row = blockIdx.x;
    int b = row / T_, t = row % T_;
    for (int l = threadIdx.x; l < LIN_; l += 128) {
        float s = 0.f;
        #pragma unroll
        for (int h = 0; h < H_; h++)
            s += block2[((size_t)(b * H_ + h) * T_ + t) * LIN_ + l];
        out2[(size_t)row * LIN_ + l] = s * 0.125f;
    }
}

__global__ void zero_tail_kernel(float* __restrict__ out) {
    int idx = blockIdx.x * blockDim.x + threadIdx.x;
    if (idx >= B_ * T_ * 100) return;
    int row = idx / 100;
    int t   = idx % 100;
    out[(size_t)row * VEXT_ + V_ + t] = 0.f;
}

__global__ void scatter_kernel(float* __restrict__ out,
                               const float* __restrict__ am,
                               const float* __restrict__ pg,
                               const int* __restrict__ ext)
{
    int idx = blockIdx.x * blockDim.x + threadIdx.x;
    if (idx >= B_ * T_ * LIN_) return;
    int l = idx % LIN_;
    int row = idx / LIN_;
    int b = row / T_;
    float q = 1.f - pg[row];
    atomicAdd(&out[(size_t)row * VEXT_ + ext[(size_t)b * LIN_ + l]],
              q * am[(size_t)row * LIN_ + l]);
}

// ---------------------------------------------------------------------------
static inline void gemmN(const float* A, const float* W, const float* bias,
                         const float* rs, float* C, int M, int Ntot, int K,
                         int ldc, int relu, int roundC,
                         int Ninner, long wgs, long bgs, long cgs) {
    if (M > 2048) {
        dim3 grid(Ntot / 128, (M + 127) / 128);
        gemm_tf32<4><<<grid, 256>>>(A, W, bias, rs, C, M, K, ldc, relu, roundC,
                                    Ninner, wgs, bgs, cgs);
    } else {
        dim3 grid(Ntot / 128, (M + 63) / 64);
        gemm_tf32<2><<<grid, 256>>>(A, W, bias, rs, C, M, K, ldc, relu, roundC,
                                    Ninner, wgs, bgs, cgs);
    }
}
static inline void gemm(const float* A, const float* W, const float* bias,
                        const float* rs, float* C, int M, int N, int K,
                        int ldc, int relu, int roundC) {
    gemmN(A, W, bias, rs, C, M, N, K, ldc, relu, roundC, N, 0, 0, 0);
}
static inline void roundw(const float* src, float* dst, long n) {
    round_bulk<<<(unsigned)((n / 4 + 255) / 256), 256>>>(src, dst, (int)(n / 4));
}

extern "C" void kernel_launch(void* const* d_in, const int* in_sizes, int n_in,
                              void* d_out, int out_size) {
    const int*   inp     = (const int*)d_in[0];
    const int*   tar     = (const int*)d_in[1];
    const int*   ext     = (const int*)d_in[2];
    const float* enc_pad = (const float*)d_in[3];
    const float* look    = (const float*)d_in[4];
    const float* dec_pad = (const float*)d_in[5];
    int o = (in_sizes[6] <= 4) ? 7 : 6;
    const float* emb_enc = (const float*)d_in[o + 0];
    const float* emb_dec = (const float*)d_in[o + 1];
    const float* eaw  = (const float*)d_in[o + 2];
    const float* eab  = (const float*)d_in[o + 3];
    const float* ew1  = (const float*)d_in[o + 4];
    const float* eb1  = (const float*)d_in[o + 5];
    const float* ew2  = (const float*)d_in[o + 6];
    const float* eb2  = (const float*)d_in[o + 7];
    const float* elng = (const float*)d_in[o + 8];
    const float* elnb = (const float*)d_in[o + 9];
    const float* daw  = (const float*)d_in[o + 10];
    const float* dab  = (const float*)d_in[o + 11];
    const float* dw1  = (const float*)d_in[o + 12];
    const float* db1  = (const float*)d_in[o + 13];
    const float* dw2  = (const float*)d_in[o + 14];
    const float* db2  = (const float*)d_in[o + 15];
    const float* dlng = (const float*)d_in[o + 16];
    const float* dlnb = (const float*)d_in[o + 17];
    const float* ptrw = (const float*)d_in[o + 18];
    const float* ptrb = (const float*)d_in[o + 19];
    const float* finw = (const float*)d_in[o + 20];
    const float* finb = (const float*)d_in[o + 21];
    float* out = (float*)d_out;

    float *pe, *encx, *qkv, *attno, *tmp, *ffn, *decx, *o1buf,
          *embedr, *block2, *ctx, *pg, *wtf;
    cudaGetSymbolAddress((void**)&pe,     g_pe);
    cudaGetSymbolAddress((void**)&encx,   g_encx);
    cudaGetSymbolAddress((void**)&qkv,    g_qkv);
    cudaGetSymbolAddress((void**)&attno,  g_attno);
    cudaGetSymbolAddress((void**)&tmp,    g_tmp);
    cudaGetSymbolAddress((void**)&ffn,    g_ffn);
    cudaGetSymbolAddress((void**)&decx,   g_decx);
    cudaGetSymbolAddress((void**)&o1buf,  g_o1);
    cudaGetSymbolAddress((void**)&embedr, g_embed);
    cudaGetSymbolAddress((void**)&block2, g_block2);
    cudaGetSymbolAddress((void**)&ctx,    g_ctx);
    cudaGetSymbolAddress((void**)&pg,     g_pg);
    cudaGetSymbolAddress((void**)&wtf,    g_wtf);

    static int attn_attr_set = 0;
    if (!attn_attr_set) {
        cudaFuncSetAttribute(attn_tiled,
                             cudaFuncAttributeMaxDynamicSharedMemorySize,
                             ATTN_SMEM);
        attn_attr_set = 1;
    }

    float* q = qkv;
    float* k = qkv + QKV_SZ;
    float* v = qkv + 2 * QKV_SZ;

    const int ME = B_ * LIN_;  // 6400
    const int MD = B_ * T_;    // 1600
    const long DD = DD_;

    // ----- pre-round all weights to tf32 (bulk, bandwidth-cheap) -----
    roundw(eaw,  wtf + O_EAW,  (long)L_ * 4 * DD);
    roundw(ew1,  wtf + O_EW1,  (long)L_ * D_ * DFF_);
    roundw(ew2,  wtf + O_EW2,  (long)L_ * DFF_ * D_);
    roundw(daw,  wtf + O_DAW,  (long)L_ * 2 * 4 * DD);
    roundw(dw1,  wtf + O_DW1,  (long)L_ * D_ * DFF_);
    roundw(dw2,  wtf + O_DW2,  (long)L_ * DFF_ * D_);
    roundw(finw, wtf + O_FINW, (long)D_ * V_);
    const float* reaw  = wtf + O_EAW;
    const float* rew1  = wtf + O_EW1;
    const float* rew2  = wtf + O_EW2;
    const float* rdaw  = wtf + O_DAW;
    const float* rdw1  = wtf + O_DW1;
    const float* rdw2  = wtf + O_DW2;
    const float* rfinw = wtf + O_FINW;

    pe_kernel<<<(LIN_ * D_ + 255) / 256, 256>>>(pe);
    embed_kernel<<<(ME * D_ + 255) / 256, 256>>>(inp, emb_enc, pe, encx,
                                                 nullptr, LIN_, ME * D_);
    embed_kernel<<<(MD * D_ + 255) / 256, 256>>>(tar, emb_dec, pe, decx,
                                                 embedr, T_, MD * D_);

    // ----- encoder -----
    for (int i = 0; i < L_; i++) {
        const float* w  = reaw + (size_t)i * 4 * DD;
        const float* bb = eab + (size_t)i * 4 * D_;
        gemmN(encx, w, bb, nullptr, q, ME, 3 * D_, D_, D_, 0, 0,
              D_, DD, D_, QKV_SZ);
        attn_tiled<<<B_ * H_ * ((LIN_ + QT - 1) / QT), 128, ATTN_SMEM>>>(
            q, k, v, enc_pad, 0, attno, nullptr, nullptr, nullptr, LIN_, LIN_);
        gemm(attno, w + 3 * DD, bb + 3 * D_, nullptr, tmp, ME, D_, D_, D_, 0, 0);
        add_ln<<<ME, 128>>>(encx, tmp, elng + (size_t)(i * 2 + 0) * D_,
                            elnb + (size_t)(i * 2 + 0) * D_, encx);
        gemm(encx, rew1 + (size_t)i * D_ * DFF_, eb1 + (size_t)i * DFF_,
             nullptr, ffn, ME, DFF_, D_, DFF_, 1, 1);
        gemm(ffn, rew2 + (size_t)i * DFF_ * D_, eb2 + (size_t)i * D_,
             nullptr, tmp, ME, D_, DFF_, D_, 0, 0);
        add_ln<<<ME, 128>>>(encx, tmp, elng + (size_t)(i * 2 + 1) * D_,
                            elnb + (size_t)(i * 2 + 1) * D_, encx);
    }

    // ----- decoder: only layer L-1 affects outputs -----
    {
        const int i = L_ - 1;
        const float* w0 = rdaw + (size_t)(i * 2 + 0) * 4 * DD;
        const float* b0 = dab + (size_t)(i * 2 + 0) * 4 * D_;
        gemmN(decx, w0, b0, nullptr, q, MD, 3 * D_, D_, D_, 0, 0,
              D_, DD, D_, QKV_SZ);
        attn_tiled<<<B_ * H_ * ((T_ + QT - 1) / QT), 128, ATTN_SMEM>>>(
            q, k, v, look, 1, attno, nullptr, nullptr, nullptr, T_, T_);
        gemm(attno, w0 + 3 * DD, b0 + 3 * D_, nullptr, tmp, MD, D_, D_, D_, 0, 0);
        add_ln<<<MD, 128>>>(decx, tmp, dlng + (size_t)(i * 3 + 0) * D_,
                            dlnb + (size_t)(i * 3 + 0) * D_, o1buf);
        const float* w1 = rdaw + (size_t)(i * 2 + 1) * 4 * DD;
        const float* b1 = dab + (size_t)(i * 2 + 1) * 4 * D_;
        gemm(o1buf, w1, b1, nullptr, q, MD, D_, D_, D_, 0, 0);
        gemmN(encx, w1 + DD, b1 + D_, nullptr, k, ME, 2 * D_, D_, D_, 0, 0,
              D_, DD, D_, QKV_SZ);
        attn_tiled<<<B_ * H_ * ((T_ + QT - 1) / QT), 128, ATTN_SMEM>>>(
            q, k, v, dec_pad, 0, attno, block2, encx, ctx, T_, LIN_);
        gemm(attno, w1 + 3 * DD, b1 + 3 * D_, nullptr, tmp, MD, D_, D_, D_, 0, 0);
        add_ln<<<MD, 128>>>(o1buf, tmp, dlng + (size_t)(i * 3 + 1) * D_,
                            dlnb + (size_t)(i * 3 + 1) * D_, o1buf);
        gemm(o1buf, rdw1 + (size_t)i * D_ * DFF_, db1 + (size_t)i * DFF_,
             nullptr, ffn, MD, DFF_, D_, DFF_, 1, 1);
        gemm(ffn, rdw2 + (size_t)i * DFF_ * D_, db2 + (size_t)i * D_,
             nullptr, tmp, MD, D_, DFF_, D_, 0, 0);
        add_ln<<<MD, 128>>>(o1buf, tmp, dlng + (size_t)(i * 3 + 2) * D_,
                            dlnb + (size_t)(i * 3 + 2) * D_, decx);
    }

    // ----- pointer-generator prob, head with fused p*logits -----
    pgen_kernel<<<MD, 128>>>(ctx, decx, embedr, ptrw, ptrb, pg);
    gemm(decx, rfinw, finb, pg, out, MD, V_, D_, VEXT_, 0, 0);
    zero_tail_kernel<<<(MD * 100 + 255) / 256, 256>>>(out);

    float* out2 = out + (size_t)MD * VEXT_;
    attn_mean_kernel<<<MD, 128>>>(block2, out2);
    scatter_kernel<<<(B_ * T_ * LIN_ + 255) / 256, 256>>>(out, out2, pg, ext);
}